// round 15
// baseline (speedup 1.0000x reference)
#include <cuda_runtime.h>

#define NN 10000
#define NE 640000
#define D  128

// Scratch: per-type aggregated features and edge counts (no cudaMalloc allowed).
__device__ __align__(16) float g_A[2][NN * D];
__device__ int g_cnt[2][NN];
__device__ int g_idx_is64;   // 1 if edge buffers are int64, 0 if int32

// ---------------------------------------------------------------------------
// Kernel 0: detect edge-index dtype. If the first 256 words interpreted as
// int64 all lie in [0, NN), the buffer is genuinely int64; int32 data would
// produce huge values (hi word in [0,10000)) with probability ~1.
// Deterministic: same input -> same flag every launch.
// ---------------------------------------------------------------------------
__global__ void detect_kernel(const void* ei) {
    if (blockIdx.x == 0 && threadIdx.x == 0) {
        const long long* p = (const long long*)ei;
        int ok = 1;
        #pragma unroll 4
        for (int i = 0; i < 256; i++) {
            long long v = p[i];
            if (v < 0 || v >= NN) { ok = 0; break; }
        }
        g_idx_is64 = ok;
    }
}

// ---------------------------------------------------------------------------
// Kernel 1: zero the accumulators.
// ---------------------------------------------------------------------------
__global__ void zero_kernel() {
    int idx = blockIdx.x * blockDim.x + threadIdx.x;
    int stride = gridDim.x * blockDim.x;
    const int total4 = 2 * NN * D / 4;
    float4 z = make_float4(0.f, 0.f, 0.f, 0.f);
    float4* a4 = reinterpret_cast<float4*>(&g_A[0][0]);
    for (int i = idx; i < total4; i += stride) a4[i] = z;
    int* c = &g_cnt[0][0];
    for (int i = idx; i < 2 * NN; i += stride) c[i] = 0;
}

// ---------------------------------------------------------------------------
// Kernel 2: scatter — one warp per edge.
// A_t[dst] += X[src] via red.global.add.v4.f32; c_t[dst] += 1.
// Handles int32 or int64 edge buffers via g_idx_is64.
// ---------------------------------------------------------------------------
__global__ void scatter_kernel(const float* __restrict__ X,
                               const void* __restrict__ ei_raw,
                               const void* __restrict__ et_raw) {
    int gw = (blockIdx.x * blockDim.x + threadIdx.x) >> 5;  // edge id
    int lane = threadIdx.x & 31;
    if (gw >= NE) return;

    int src, dst, t;
    if (g_idx_is64) {
        const long long* ei = (const long long*)ei_raw;
        const long long* et = (const long long*)et_raw;
        src = (int)ei[gw];
        dst = (int)ei[NE + gw];
        t   = (int)et[gw];
    } else {
        const int* ei = (const int*)ei_raw;
        const int* et = (const int*)et_raw;
        src = ei[gw];
        dst = ei[NE + gw];
        t   = et[gw];
    }
    // Safety clamps: an out-of-range index becomes a rel_err, not a crash.
    src = min(max(src, 0), NN - 1);
    dst = min(max(dst, 0), NN - 1);
    t   = t & 1;

    float4 v = reinterpret_cast<const float4*>(X + (size_t)src * D)[lane];
    float* a = &g_A[t][(size_t)dst * D + lane * 4];
    asm volatile("red.global.add.v4.f32 [%0], {%1, %2, %3, %4};"
                 :: "l"(a), "f"(v.x), "f"(v.y), "f"(v.z), "f"(v.w)
                 : "memory");
    if (lane == 0) atomicAdd(&g_cnt[t][dst], 1);
}

// ---------------------------------------------------------------------------
// Kernel 3: fused GEMM + bias + relu.
// out[n] = relu( X[n]@Ws^T + A0[n]@Wd^T + A1[n]@Wc^T + bs + c0[n]*bd + c1[n]*bc )
// Tile: 32 nodes x 128 outs per block, 256 threads, 4x4 accumulators/thread.
// ---------------------------------------------------------------------------
#define TN 32
#define KC 32

__global__ __launch_bounds__(256)
void gemm_kernel(const float* __restrict__ X,
                 const float* __restrict__ Wd, const float* __restrict__ bd,
                 const float* __restrict__ Wc, const float* __restrict__ bc,
                 const float* __restrict__ Ws, const float* __restrict__ bs,
                 float* __restrict__ out) {
    __shared__ float in_s[TN][KC];      // [node][k] — read is warp-broadcast
    __shared__ float w_s[D][KC + 1];    // [o][k] padded: conflict-free column reads

    int tid = threadIdx.x;
    int lane = tid & 31;
    int ng = tid >> 5;                  // 0..7, 4 nodes each
    int n_base = blockIdx.x * TN;

    float acc[4][4];
    #pragma unroll
    for (int i = 0; i < 4; i++)
        #pragma unroll
        for (int j = 0; j < 4; j++) acc[i][j] = 0.f;

    const float* in_srcs[3] = {X, &g_A[0][0], &g_A[1][0]};
    const float* w_srcs[3]  = {Ws, Wd, Wc};

    #pragma unroll 1
    for (int c = 0; c < 12; c++) {
        int seg = c >> 2;                 // which (input, weight) pair
        int kb  = (c & 3) * KC;           // k offset within the 128-dim
        const float* insrc = in_srcs[seg];
        const float* wsrc  = w_srcs[seg];

        __syncthreads();
        // Input tile: 32 nodes x 32 k, one float4 per thread.
        {
            int node = tid >> 3;          // 0..31
            int ko   = (tid & 7) * 4;
            int gn   = n_base + node;
            float4 v = make_float4(0.f, 0.f, 0.f, 0.f);
            if (gn < NN)
                v = *reinterpret_cast<const float4*>(insrc + (size_t)gn * D + kb + ko);
            *reinterpret_cast<float4*>(&in_s[node][ko]) = v;
        }
        // Weight tile: 128 o x 32 k, 16 floats per thread into padded rows.
        {
            int o  = tid >> 1;            // 0..127
            int kh = (tid & 1) * 16;      // 0 or 16
            const float* wrow = wsrc + (size_t)o * D + kb + kh;
            #pragma unroll
            for (int j = 0; j < 16; j += 4) {
                float4 v = *reinterpret_cast<const float4*>(wrow + j);
                w_s[o][kh + j + 0] = v.x;
                w_s[o][kh + j + 1] = v.y;
                w_s[o][kh + j + 2] = v.z;
                w_s[o][kh + j + 3] = v.w;
            }
        }
        __syncthreads();

        #pragma unroll
        for (int kk = 0; kk < KC; kk++) {
            float wv[4];
            #pragma unroll
            for (int j = 0; j < 4; j++) wv[j] = w_s[lane + j * 32][kk];
            #pragma unroll
            for (int i = 0; i < 4; i++) {
                float iv = in_s[ng * 4 + i][kk];
                #pragma unroll
                for (int j = 0; j < 4; j++)
                    acc[i][j] = fmaf(iv, wv[j], acc[i][j]);
            }
        }
    }

    // Epilogue: bias (incl. per-type edge-count * bias) + relu, coalesced.
    #pragma unroll
    for (int i = 0; i < 4; i++) {
        int n = n_base + ng * 4 + i;
        if (n >= NN) continue;
        float c0 = (float)g_cnt[0][n];
        float c1 = (float)g_cnt[1][n];
        #pragma unroll
        for (int j = 0; j < 4; j++) {
            int o = lane + j * 32;
            float r = acc[i][j] + bs[o] + c0 * bd[o] + c1 * bc[o];
            out[(size_t)n * D + o] = fmaxf(r, 0.f);
        }
    }
}

// ---------------------------------------------------------------------------
// Launch
// ---------------------------------------------------------------------------
extern "C" void kernel_launch(void* const* d_in, const int* in_sizes, int n_in,
                              void* d_out, int out_size) {
    const float* X  = (const float*)d_in[0];
    const void*  ei = d_in[1];
    const void*  et = d_in[2];
    const float* Wd = (const float*)d_in[3];
    const float* bd = (const float*)d_in[4];
    const float* Wc = (const float*)d_in[5];
    const float* bc = (const float*)d_in[6];
    const float* Ws = (const float*)d_in[7];
    const float* bs = (const float*)d_in[8];
    float* out = (float*)d_out;

    detect_kernel<<<1, 32>>>(ei);
    zero_kernel<<<592, 256>>>();
    scatter_kernel<<<(NE * 32) / 256, 256>>>(X, ei, et);
    gemm_kernel<<<(NN + TN - 1) / TN, 256>>>(X, Wd, bd, Wc, bc, Ws, bs, out);
}

// round 16
// speedup vs baseline: 1.0055x; 1.0055x over previous
#include <cuda_runtime.h>

#define NN 10000
#define NE 640000
#define D  128

// Scratch: per-type aggregated features and edge counts (no cudaMalloc allowed).
__device__ __align__(16) float g_A[2][NN * D];
__device__ int g_cnt[2][NN];
__device__ int g_idx_is64;   // 1 if edge buffers are int64, 0 if int32

// ---------------------------------------------------------------------------
// Kernel 0: detect edge-index dtype. If the first 256 words interpreted as
// int64 all lie in [0, NN), the buffer is genuinely int64; int32 data would
// produce huge values (hi word in [0,10000)) with probability ~1.
// Deterministic: same input -> same flag every launch.
// ---------------------------------------------------------------------------
__global__ void detect_kernel(const void* ei) {
    if (blockIdx.x == 0 && threadIdx.x == 0) {
        const long long* p = (const long long*)ei;
        int ok = 1;
        #pragma unroll 4
        for (int i = 0; i < 256; i++) {
            long long v = p[i];
            if (v < 0 || v >= NN) { ok = 0; break; }
        }
        g_idx_is64 = ok;
    }
}

// ---------------------------------------------------------------------------
// Kernel 1: zero the accumulators.
// ---------------------------------------------------------------------------
__global__ void zero_kernel() {
    int idx = blockIdx.x * blockDim.x + threadIdx.x;
    int stride = gridDim.x * blockDim.x;
    const int total4 = 2 * NN * D / 4;
    float4 z = make_float4(0.f, 0.f, 0.f, 0.f);
    float4* a4 = reinterpret_cast<float4*>(&g_A[0][0]);
    for (int i = idx; i < total4; i += stride) a4[i] = z;
    int* c = &g_cnt[0][0];
    for (int i = idx; i < 2 * NN; i += stride) c[i] = 0;
}

// ---------------------------------------------------------------------------
// Kernel 2: scatter — one warp per edge.
// A_t[dst] += X[src] via red.global.add.v4.f32; c_t[dst] += 1.
// Handles int32 or int64 edge buffers via g_idx_is64.
// ---------------------------------------------------------------------------
__global__ void scatter_kernel(const float* __restrict__ X,
                               const void* __restrict__ ei_raw,
                               const void* __restrict__ et_raw) {
    int gw = (blockIdx.x * blockDim.x + threadIdx.x) >> 5;  // edge id
    int lane = threadIdx.x & 31;
    if (gw >= NE) return;

    int src, dst, t;
    if (g_idx_is64) {
        const long long* ei = (const long long*)ei_raw;
        const long long* et = (const long long*)et_raw;
        src = (int)ei[gw];
        dst = (int)ei[NE + gw];
        t   = (int)et[gw];
    } else {
        const int* ei = (const int*)ei_raw;
        const int* et = (const int*)et_raw;
        src = ei[gw];
        dst = ei[NE + gw];
        t   = et[gw];
    }
    // Safety clamps: an out-of-range index becomes a rel_err, not a crash.
    src = min(max(src, 0), NN - 1);
    dst = min(max(dst, 0), NN - 1);
    t   = t & 1;

    float4 v = reinterpret_cast<const float4*>(X + (size_t)src * D)[lane];
    float* a = &g_A[t][(size_t)dst * D + lane * 4];
    asm volatile("red.global.add.v4.f32 [%0], {%1, %2, %3, %4};"
                 :: "l"(a), "f"(v.x), "f"(v.y), "f"(v.z), "f"(v.w)
                 : "memory");
    if (lane == 0) atomicAdd(&g_cnt[t][dst], 1);
}

// ---------------------------------------------------------------------------
// Kernel 3: fused GEMM + bias + relu.
// out[n] = relu( X[n]@Ws^T + A0[n]@Wd^T + A1[n]@Wc^T + bs + c0[n]*bd + c1[n]*bc )
// Tile: 32 nodes x 128 outs per block, 256 threads, 4x4 accumulators/thread.
// ---------------------------------------------------------------------------
#define TN 32
#define KC 32

__global__ __launch_bounds__(256)
void gemm_kernel(const float* __restrict__ X,
                 const float* __restrict__ Wd, const float* __restrict__ bd,
                 const float* __restrict__ Wc, const float* __restrict__ bc,
                 const float* __restrict__ Ws, const float* __restrict__ bs,
                 float* __restrict__ out) {
    __shared__ float in_s[TN][KC];      // [node][k] — read is warp-broadcast
    __shared__ float w_s[D][KC + 1];    // [o][k] padded: conflict-free column reads

    int tid = threadIdx.x;
    int lane = tid & 31;
    int ng = tid >> 5;                  // 0..7, 4 nodes each
    int n_base = blockIdx.x * TN;

    float acc[4][4];
    #pragma unroll
    for (int i = 0; i < 4; i++)
        #pragma unroll
        for (int j = 0; j < 4; j++) acc[i][j] = 0.f;

    const float* in_srcs[3] = {X, &g_A[0][0], &g_A[1][0]};
    const float* w_srcs[3]  = {Ws, Wd, Wc};

    #pragma unroll 1
    for (int c = 0; c < 12; c++) {
        int seg = c >> 2;                 // which (input, weight) pair
        int kb  = (c & 3) * KC;           // k offset within the 128-dim
        const float* insrc = in_srcs[seg];
        const float* wsrc  = w_srcs[seg];

        __syncthreads();
        // Input tile: 32 nodes x 32 k, one float4 per thread.
        {
            int node = tid >> 3;          // 0..31
            int ko   = (tid & 7) * 4;
            int gn   = n_base + node;
            float4 v = make_float4(0.f, 0.f, 0.f, 0.f);
            if (gn < NN)
                v = *reinterpret_cast<const float4*>(insrc + (size_t)gn * D + kb + ko);
            *reinterpret_cast<float4*>(&in_s[node][ko]) = v;
        }
        // Weight tile: 128 o x 32 k, 16 floats per thread into padded rows.
        {
            int o  = tid >> 1;            // 0..127
            int kh = (tid & 1) * 16;      // 0 or 16
            const float* wrow = wsrc + (size_t)o * D + kb + kh;
            #pragma unroll
            for (int j = 0; j < 16; j += 4) {
                float4 v = *reinterpret_cast<const float4*>(wrow + j);
                w_s[o][kh + j + 0] = v.x;
                w_s[o][kh + j + 1] = v.y;
                w_s[o][kh + j + 2] = v.z;
                w_s[o][kh + j + 3] = v.w;
            }
        }
        __syncthreads();

        #pragma unroll
        for (int kk = 0; kk < KC; kk++) {
            float wv[4];
            #pragma unroll
            for (int j = 0; j < 4; j++) wv[j] = w_s[lane + j * 32][kk];
            #pragma unroll
            for (int i = 0; i < 4; i++) {
                float iv = in_s[ng * 4 + i][kk];
                #pragma unroll
                for (int j = 0; j < 4; j++)
                    acc[i][j] = fmaf(iv, wv[j], acc[i][j]);
            }
        }
    }

    // Epilogue: bias (incl. per-type edge-count * bias) + relu, coalesced.
    #pragma unroll
    for (int i = 0; i < 4; i++) {
        int n = n_base + ng * 4 + i;
        if (n >= NN) continue;
        float c0 = (float)g_cnt[0][n];
        float c1 = (float)g_cnt[1][n];
        #pragma unroll
        for (int j = 0; j < 4; j++) {
            int o = lane + j * 32;
            float r = acc[i][j] + bs[o] + c0 * bd[o] + c1 * bc[o];
            out[(size_t)n * D + o] = fmaxf(r, 0.f);
        }
    }
}

// ---------------------------------------------------------------------------
// Launch
// ---------------------------------------------------------------------------
extern "C" void kernel_launch(void* const* d_in, const int* in_sizes, int n_in,
                              void* d_out, int out_size) {
    const float* X  = (const float*)d_in[0];
    const void*  ei = d_in[1];
    const void*  et = d_in[2];
    const float* Wd = (const float*)d_in[3];
    const float* bd = (const float*)d_in[4];
    const float* Wc = (const float*)d_in[5];
    const float* bc = (const float*)d_in[6];
    const float* Ws = (const float*)d_in[7];
    const float* bs = (const float*)d_in[8];
    float* out = (float*)d_out;

    detect_kernel<<<1, 32>>>(ei);
    zero_kernel<<<592, 256>>>();
    scatter_kernel<<<(NE * 32) / 256, 256>>>(X, ei, et);
    gemm_kernel<<<(NN + TN - 1) / TN, 256>>>(X, Wd, bd, Wc, bc, Ws, bs, out);
}